// round 5
// baseline (speedup 1.0000x reference)
#include <cuda_runtime.h>
#include <math.h>

// LearnableKalmanTracker.
//  Kernel 1 (riccati_kernel): batch-invariant covariance/gain recursion ->
//    K_t table, bitwise-exact early freeze (period-1/2).
//  Kernel 2 (consumer_kernel): affine-in-w step (R4) + dual-sequence
//    interleave (R5): each lane-quad carries TWO independent sequences,
//    phase-interleaved so one fills the other's exposed stall latency
//    (shfl/MUFU chains), pushing the warp toward its fma-issue floor.
// H_base = [I4|0] exploited analytically.

#define T_STEPS 512
#define FULLM 0xffffffffu

__device__ float g_Kall[T_STEPS * 32];   // K_t (8x4) flattened

__device__ __forceinline__ float sigmoid_fast(float x) {
    return __fdividef(1.0f, 1.0f + __expf(-x));
}

// ---------------- Kernel 1: shared Riccati recursion (32 threads) ----------
__global__ void __launch_bounds__(32)
riccati_kernel(const float* __restrict__ F_diag, const float* __restrict__ F_vel,
               const float* __restrict__ q_scale, const float* __restrict__ r_scale)
{
    __shared__ float C[64], P[64], Sinv[16], Ksh[32], fdv[8], fvv[4];
    const int lane = threadIdx.x;

    if (lane < 8) fdv[lane] = fminf(fmaxf(F_diag[lane], 0.9f), 1.1f);
    if (lane < 4) fvv[lane] = 1.0f / (1.0f + expf(-F_vel[lane]));
    const float qv = expf(q_scale[0]);
    const float rv = expf(r_scale[0]);

    const int e0 = lane, e1 = lane + 32;
    C[e0] = ((e0 >> 3) == (e0 & 7)) ? 1.0f : 0.0f;
    C[e1] = ((e1 >> 3) == (e1 & 7)) ? 1.0f : 0.0f;
    __syncwarp();

    float cold1_a = C[e0], cold1_b = C[e1];
    float cold2_a = 0.f,   cold2_b = 0.f;

    for (int t = 1; t < T_STEPS; ++t) {
#pragma unroll
        for (int h = 0; h < 2; h++) {
            int e = lane + h * 32;
            int i = e >> 3, j = e & 7;
            float fdi = fdv[i], fdj = fdv[j];
            float v = fdi * fdj * C[i * 8 + j];
            if (j < 4) v += fdi * fvv[j] * C[i * 8 + j + 4];
            if (i < 4) {
                float fvi = fvv[i];
                v += fvi * fdj * C[(i + 4) * 8 + j];
                if (j < 4) v += fvi * fvv[j] * C[(i + 4) * 8 + j + 4];
            }
            if (i == j) v += qv;
            P[e] = v;
        }
        __syncwarp();

        {
            int a = (lane >> 2) & 3, b = lane & 3;
            int r0 = 0 + (0 >= a), r1 = 1 + (1 >= a), r2 = 2 + (2 >= a);
            int c0 = 0 + (0 >= b), c1 = 1 + (1 >= b), c2 = 2 + (2 >= b);
            auto S = [&](int x, int y) -> float {
                float v = P[x * 8 + y];
                return (x == y) ? v + rv : v;
            };
            float m00 = S(r0, c0), m01 = S(r0, c1), m02 = S(r0, c2);
            float m10 = S(r1, c0), m11 = S(r1, c1), m12 = S(r1, c2);
            float m20 = S(r2, c0), m21 = S(r2, c1), m22 = S(r2, c2);
            float det3 = m00 * (m11 * m22 - m12 * m21)
                       - m01 * (m10 * m22 - m12 * m20)
                       + m02 * (m10 * m21 - m11 * m20);
            float cof = ((a + b) & 1) ? -det3 : det3;
            float c0v = __shfl_sync(FULLM, cof, 0);
            float c1v = __shfl_sync(FULLM, cof, 4);
            float c2v = __shfl_sync(FULLM, cof, 8);
            float c3v = __shfl_sync(FULLM, cof, 12);
            float det = S(0, 0) * c0v + S(1, 0) * c1v + S(2, 0) * c2v + S(3, 0) * c3v;
            float idet = __fdividef(1.0f, det);
            if (lane < 16) Sinv[b * 4 + a] = cof * idet;
        }
        __syncwarp();

        {
            int i = lane >> 2, m = lane & 3;
            float kv = P[i * 8 + 0] * Sinv[0 * 4 + m]
                     + P[i * 8 + 1] * Sinv[1 * 4 + m]
                     + P[i * 8 + 2] * Sinv[2 * 4 + m]
                     + P[i * 8 + 3] * Sinv[3 * 4 + m];
            Ksh[lane] = kv;
            g_Kall[t * 32 + lane] = kv;
        }
        __syncwarp();

        float na, nb;
        {
            int i0 = e0 >> 3, j0 = e0 & 7;
            float v = P[e0];
            v -= Ksh[i0 * 4 + 0] * P[0 * 8 + j0];
            v -= Ksh[i0 * 4 + 1] * P[1 * 8 + j0];
            v -= Ksh[i0 * 4 + 2] * P[2 * 8 + j0];
            v -= Ksh[i0 * 4 + 3] * P[3 * 8 + j0];
            na = v;
            int i1 = e1 >> 3, j1 = e1 & 7;
            float u = P[e1];
            u -= Ksh[i1 * 4 + 0] * P[0 * 8 + j1];
            u -= Ksh[i1 * 4 + 1] * P[1 * 8 + j1];
            u -= Ksh[i1 * 4 + 2] * P[2 * 8 + j1];
            u -= Ksh[i1 * 4 + 3] * P[3 * 8 + j1];
            nb = u;
        }
        int conv1 = __all_sync(FULLM, (na == cold1_a) && (nb == cold1_b));
        int conv2 = __all_sync(FULLM, (na == cold2_a) && (nb == cold2_b)) && (t >= 3);
        cold2_a = cold1_a; cold2_b = cold1_b;
        cold1_a = na;      cold1_b = nb;
        C[e0] = na; C[e1] = nb;
        __syncwarp();

        if (conv1) {
            float kA = Ksh[lane];
            for (int u = t + 1; u < T_STEPS; ++u) g_Kall[u * 32 + lane] = kA;
            return;
        }
        if (conv2) {
            float kA = Ksh[lane];
            float kB = g_Kall[(t - 1) * 32 + lane];
            for (int u = t + 1; u < T_STEPS; ++u)
                g_Kall[u * 32 + lane] = ((u - t) & 1) ? kB : kA;
            return;
        }
    }
}

// ---------------- Kernel 2: dual-sequence affine consumers -----------------

__device__ __forceinline__ float qsel(float4 v, int q) {
    float lo = (q & 1) ? v.y : v.x;
    float hi = (q & 1) ? v.w : v.z;
    return (q & 2) ? hi : lo;
}
__device__ __forceinline__ float qred(float v) {
    v += __shfl_xor_sync(FULLM, v, 1, 4);
    v += __shfl_xor_sync(FULLM, v, 2, 4);
    return v;
}
__device__ __forceinline__ float dot4(float4 a, float x0, float x1, float x2, float x3) {
    return fmaf(a.w, x3, fmaf(a.z, x2, fmaf(a.y, x1, a.x * x0)));
}

struct Cst {
    float fdq, fdq4, fvq, smw, b2s;
    float w1a[4][4], w1b[4][4], b1v[4], g1v[4], bev[4], w2v[4];
};

struct St {                               // persistent per-sequence state
    const float4* zr; float* outp;
    float4 znext, kcur0, kcur1;
    float PAq, PAq4, PBq, PBq4;
    float G1q, G1q4, G2q, G2q4;
    float C0, C1, C2;
    float PG[4], QG[4];
    float wprev;
};

struct Scr {                              // per-step scratch
    float4 zfut, kf0, kf1;
    float w;
    float pq, pq4, knq, knq4;
    float Fpq, Fpq4, Fkq, Fkq4;
    float z0_, z1_, z2_, z3_, g0_, g1_, g2_, g3_;
};

__device__ __forceinline__ void ph_pre(St& S, Scr& R, const float4* K4, int s, int q) {
    int fi = s + 2; if (fi > T_STEPS - 1) fi = T_STEPS - 1;
    R.zfut = __ldg(&S.zr[fi]);
    R.kf0  = __ldg(&K4[fi * 8 + q]);
    R.kf1  = __ldg(&K4[fi * 8 + 4 + q]);
}

__device__ __forceinline__ void ph_chain(St& S, Scr& R, const Cst& C) {
    float wp = S.wprev;
    float var  = fmaf(S.C2, wp * wp, fmaf(S.C1, wp, S.C0));   // includes +eps
    float rstd = rsqrtf(var);
    float t0 = fmaf(S.QG[0], wp, S.PG[0]);
    float t1 = fmaf(S.QG[1], wp, S.PG[1]);
    float t2 = fmaf(S.QG[2], wp, S.PG[2]);
    float t3 = fmaf(S.QG[3], wp, S.PG[3]);
    float n0 = fmaxf(fmaf(t0, rstd, C.bev[0]), 0.f) * C.w2v[0];
    float n1 = fmaxf(fmaf(t1, rstd, C.bev[1]), 0.f) * C.w2v[1];
    float n2 = fmaxf(fmaf(t2, rstd, C.bev[2]), 0.f) * C.w2v[2];
    float n3 = fmaxf(fmaf(t3, rstd, C.bev[3]), 0.f) * C.w2v[3];
    float y  = (n0 + n1) + (n2 + n3);
    y += __shfl_xor_sync(FULLM, y, 1, 4);
    y += __shfl_xor_sync(FULLM, y, 2, 4);
    R.w = sigmoid_fast(y + C.b2s) * C.smw;
}

__device__ __forceinline__ void ph_conc(St& S, Scr& R, const Cst& C, int s, int q) {
    float wp = S.wprev;
    R.pq   = fmaf(wp, S.PBq,  S.PAq);
    R.pq4  = fmaf(wp, S.PBq4, S.PAq4);
    R.knq  = fmaf(wp, S.G2q,  S.G1q);
    R.knq4 = fmaf(wp, S.G2q4, S.G1q4);
    S.outp[s * 4 + q] = fmaf(R.w, R.knq, R.pq);
    R.Fpq  = fmaf(C.fvq, R.pq4,  C.fdq * R.pq);
    R.Fpq4 = C.fdq4 * R.pq4;
    R.Fkq  = fmaf(C.fvq, R.knq4, C.fdq * R.knq);
    R.Fkq4 = C.fdq4 * R.knq4;
}

__device__ __forceinline__ void ph_shfl(St& S, Scr& R, int q) {
    float zq = qsel(S.znext, q) - R.Fpq;
    R.z0_ = __shfl_sync(FULLM, zq, 0, 4);
    R.z1_ = __shfl_sync(FULLM, zq, 1, 4);
    R.z2_ = __shfl_sync(FULLM, zq, 2, 4);
    R.z3_ = __shfl_sync(FULLM, zq, 3, 4);
    R.g0_ = __shfl_sync(FULLM, R.Fkq, 0, 4);
    R.g1_ = __shfl_sync(FULLM, R.Fkq, 1, 4);
    R.g2_ = __shfl_sync(FULLM, R.Fkq, 2, 4);
    R.g3_ = __shfl_sync(FULLM, R.Fkq, 3, 4);
}

__device__ __forceinline__ void ph_coeff(St& S, Scr& R, const Cst& C) {
    // kin_{s+1} = G1 + w_s G2 ; p_{s+1} = PA + w_s PB
    S.G1q  = dot4(S.kcur0, R.z0_, R.z1_, R.z2_, R.z3_);
    S.G1q4 = dot4(S.kcur1, R.z0_, R.z1_, R.z2_, R.z3_);
    S.G2q  = -dot4(S.kcur0, R.g0_, R.g1_, R.g2_, R.g3_);
    S.G2q4 = -dot4(S.kcur1, R.g0_, R.g1_, R.g2_, R.g3_);
    S.PAq = R.Fpq; S.PAq4 = R.Fpq4; S.PBq = R.Fkq; S.PBq4 = R.Fkq4;

    float Av[4], Bv[4];
#pragma unroll
    for (int k = 0; k < 4; k++) {
        float a = fmaf(C.w1b[k][0], S.znext.x, C.b1v[k]);
        a = fmaf(C.w1b[k][1], S.znext.y, a);
        a = fmaf(C.w1b[k][2], S.znext.z, a);
        a = fmaf(C.w1b[k][3], S.znext.w, a);
        a = fmaf(C.w1a[k][0], R.z0_, a);
        a = fmaf(C.w1a[k][1], R.z1_, a);
        a = fmaf(C.w1a[k][2], R.z2_, a);
        a = fmaf(C.w1a[k][3], R.z3_, a);
        Av[k] = a;
        float bb = C.w1a[k][0] * R.g0_;
        bb = fmaf(C.w1a[k][1], R.g1_, bb);
        bb = fmaf(C.w1a[k][2], R.g2_, bb);
        bb = fmaf(C.w1a[k][3], R.g3_, bb);
        Bv[k] = -bb;
    }
    float sa  = (Av[0] + Av[1]) + (Av[2] + Av[3]);
    float sb  = (Bv[0] + Bv[1]) + (Bv[2] + Bv[3]);
    float saa = fmaf(Av[0], Av[0], fmaf(Av[1], Av[1], fmaf(Av[2], Av[2], Av[3] * Av[3])));
    float sab = fmaf(Av[0], Bv[0], fmaf(Av[1], Bv[1], fmaf(Av[2], Bv[2], Av[3] * Bv[3])));
    float sbb = fmaf(Bv[0], Bv[0], fmaf(Bv[1], Bv[1], fmaf(Bv[2], Bv[2], Bv[3] * Bv[3])));
    sa = qred(sa); sb = qred(sb); saa = qred(saa); sab = qred(sab); sbb = qred(sbb);
    float mA = sa * 0.0625f, mB = sb * 0.0625f;
    S.C0 = fmaf(-mA, mA, fmaf(saa, 0.0625f, 1e-5f));
    S.C1 = 2.0f * fmaf(-mA, mB, sab * 0.0625f);
    S.C2 = fmaf(-mB, mB, sbb * 0.0625f);
#pragma unroll
    for (int k = 0; k < 4; k++) {
        S.PG[k] = (Av[k] - mA) * C.g1v[k];
        S.QG[k] = (Bv[k] - mB) * C.g1v[k];
    }
    S.znext = R.zfut; S.kcur0 = R.kf0; S.kcur1 = R.kf1; S.wprev = R.w;
}

__device__ __forceinline__ void prolog(St& S, const Cst& C, const float4* K4,
                                       const float* meas, float* out, int b, int q) {
    S.zr   = (const float4*)(meas + (size_t)b * T_STEPS * 4);
    S.outp = out + (size_t)b * T_STEPS * 4;
    float4 z0v = __ldg(&S.zr[0]);
    float4 z1v = __ldg(&S.zr[1]);
    float z0q = qsel(z0v, q);
    S.outp[q] = z0q;

    S.PAq = C.fdq * z0q; S.PAq4 = 0.f; S.PBq = 0.f; S.PBq4 = 0.f;

    float zfq = qsel(z1v, q) - S.PAq;
    float zf0 = __shfl_sync(FULLM, zfq, 0, 4);
    float zf1 = __shfl_sync(FULLM, zfq, 1, 4);
    float zf2 = __shfl_sync(FULLM, zfq, 2, 4);
    float zf3 = __shfl_sync(FULLM, zfq, 3, 4);

    float4 k1r0 = __ldg(&K4[1 * 8 + q]);
    float4 k1r1 = __ldg(&K4[1 * 8 + 4 + q]);
    S.G1q  = dot4(k1r0, zf0, zf1, zf2, zf3);
    S.G1q4 = dot4(k1r1, zf0, zf1, zf2, zf3);
    S.G2q = 0.f; S.G2q4 = 0.f;

    float Av[4];
#pragma unroll
    for (int k = 0; k < 4; k++) {
        float a = fmaf(C.w1b[k][0], z1v.x, C.b1v[k]);
        a = fmaf(C.w1b[k][1], z1v.y, a);
        a = fmaf(C.w1b[k][2], z1v.z, a);
        a = fmaf(C.w1b[k][3], z1v.w, a);
        a = fmaf(C.w1a[k][0], zf0, a);
        a = fmaf(C.w1a[k][1], zf1, a);
        a = fmaf(C.w1a[k][2], zf2, a);
        a = fmaf(C.w1a[k][3], zf3, a);
        Av[k] = a;
    }
    float sa  = qred((Av[0] + Av[1]) + (Av[2] + Av[3]));
    float saa = qred(fmaf(Av[0], Av[0], fmaf(Av[1], Av[1],
                 fmaf(Av[2], Av[2], Av[3] * Av[3]))));
    float mA = sa * 0.0625f;
    S.C0 = fmaf(-mA, mA, fmaf(saa, 0.0625f, 1e-5f));
    S.C1 = 0.f; S.C2 = 0.f;
#pragma unroll
    for (int k = 0; k < 4; k++) { S.PG[k] = (Av[k] - mA) * C.g1v[k]; S.QG[k] = 0.f; }

    S.kcur0 = __ldg(&K4[2 * 8 + q]);
    S.kcur1 = __ldg(&K4[2 * 8 + 4 + q]);
    S.znext = __ldg(&S.zr[2]);
    S.wprev = 0.f;
}

__global__ void __launch_bounds__(64, 1)
consumer_kernel(const float* __restrict__ meas,
                const float* __restrict__ F_diag,
                const float* __restrict__ F_vel,
                const float* __restrict__ mw,
                const float* __restrict__ W1,
                const float* __restrict__ b1,
                const float* __restrict__ g1,
                const float* __restrict__ be1,
                const float* __restrict__ W2,
                const float* __restrict__ b2,
                float* __restrict__ out)
{
    const int lane = threadIdx.x & 31;
    const int warp = threadIdx.x >> 5;
    const int q    = lane & 3;
    const int bBase = (blockIdx.x * 2 + warp) * 16;
    const int bA = bBase + (lane >> 2);
    const int bB = bA + 8;

    Cst C;
    C.fdq  = fminf(fmaxf(F_diag[q], 0.9f), 1.1f);
    C.fdq4 = fminf(fmaxf(F_diag[q + 4], 0.9f), 1.1f);
    C.fvq  = 1.0f / (1.0f + expf(-F_vel[q]));
    C.smw  = 1.0f / (1.0f + expf(-mw[0]));
    C.b2s  = b2[0];
#pragma unroll
    for (int k = 0; k < 4; k++) {
        int u = 4 * q + k;
#pragma unroll
        for (int j = 0; j < 4; j++) {
            C.w1a[k][j] = W1[u * 8 + j];
            C.w1b[k][j] = W1[u * 8 + 4 + j];
        }
        C.b1v[k] = b1[u]; C.g1v[k] = g1[u]; C.bev[k] = be1[u]; C.w2v[k] = W2[u];
    }

    const float4* K4 = (const float4*)g_Kall;

    St A, B;
    prolog(A, C, K4, meas, out, bA, q);
    prolog(B, C, K4, meas, out, bB, q);

    for (int s = 1; s < T_STEPS; ++s) {
        Scr RA, RB;
        ph_pre(A, RA, K4, s, q);   ph_pre(B, RB, K4, s, q);
        ph_chain(A, RA, C);        ph_chain(B, RB, C);
        ph_conc(A, RA, C, s, q);   ph_conc(B, RB, C, s, q);
        ph_shfl(A, RA, q);         ph_shfl(B, RB, q);
        ph_coeff(A, RA, C);        ph_coeff(B, RB, C);
    }
}

extern "C" void kernel_launch(void* const* d_in, const int* in_sizes, int n_in,
                              void* d_out, int out_size) {
    const float* meas    = (const float*)d_in[0];
    const float* F_diag  = (const float*)d_in[1];
    const float* F_vel   = (const float*)d_in[2];
    // d_in[3] = H_base ([I4|0], exploited analytically)
    const float* q_scale = (const float*)d_in[4];
    const float* r_scale = (const float*)d_in[5];
    const float* mw      = (const float*)d_in[6];
    const float* W1      = (const float*)d_in[7];
    const float* b1      = (const float*)d_in[8];
    const float* g1      = (const float*)d_in[9];
    const float* be1     = (const float*)d_in[10];
    const float* W2      = (const float*)d_in[11];
    const float* b2      = (const float*)d_in[12];
    float* out = (float*)d_out;

    riccati_kernel<<<1, 32>>>(F_diag, F_vel, q_scale, r_scale);

    int B = in_sizes[0] / (T_STEPS * 4);           // 2048
    dim3 grid(B / 32);                             // 64 blocks x 2 warps, 16 seq/warp
    consumer_kernel<<<grid, 64>>>(
        meas, F_diag, F_vel, mw, W1, b1, g1, be1, W2, b2, out);
}

// round 6
// speedup vs baseline: 1.6184x; 1.6184x over previous
#include <cuda_runtime.h>
#include <math.h>

// LearnableKalmanTracker.
//  Kernel 1 (riccati_kernel): batch-invariant covariance/gain recursion ->
//    K_t table, bitwise-exact early freeze (period-1/2).
//  Kernel 2 (consumer_kernel): affine-in-w step (R4) with Blackwell packed
//    f32x2 math (R6): fma.rn.f32x2 halves the fma-pipe issue count of the
//    off-chain coefficient build; serial w-chain stays scalar (latency-bound).
//    One sequence per lane-quad, 8 seqs/warp, 256 warps (per-warp latency is
//    the wall clock here -- SMs are not saturated, so never add work per warp).
// H_base = [I4|0] exploited analytically.

#define T_STEPS 512
#define FULLM 0xffffffffu

__device__ float g_Kall[T_STEPS * 32];   // K_t (8x4) flattened

typedef unsigned long long u64p;

__device__ __forceinline__ u64p pk2(float lo, float hi) {
    u64p r; asm("mov.b64 %0, {%1, %2};" : "=l"(r) : "f"(lo), "f"(hi)); return r;
}
__device__ __forceinline__ void upk2(u64p v, float& lo, float& hi) {
    asm("mov.b64 {%0, %1}, %2;" : "=f"(lo), "=f"(hi) : "l"(v));
}
__device__ __forceinline__ u64p ffma2(u64p a, u64p b, u64p c) {
    u64p d; asm("fma.rn.f32x2 %0, %1, %2, %3;" : "=l"(d) : "l"(a), "l"(b), "l"(c)); return d;
}
__device__ __forceinline__ u64p fmul2(u64p a, u64p b) {
    u64p d; asm("mul.rn.f32x2 %0, %1, %2;" : "=l"(d) : "l"(a), "l"(b)); return d;
}
__device__ __forceinline__ u64p fadd2(u64p a, u64p b) {
    u64p d; asm("add.rn.f32x2 %0, %1, %2;" : "=l"(d) : "l"(a), "l"(b)); return d;
}

__device__ __forceinline__ float sigmoid_fast(float x) {
    return __fdividef(1.0f, 1.0f + __expf(-x));
}

// ---------------- Kernel 1: shared Riccati recursion (32 threads) ----------
__global__ void __launch_bounds__(32)
riccati_kernel(const float* __restrict__ F_diag, const float* __restrict__ F_vel,
               const float* __restrict__ q_scale, const float* __restrict__ r_scale)
{
    __shared__ float C[64], P[64], Sinv[16], Ksh[32], fdv[8], fvv[4];
    const int lane = threadIdx.x;

    if (lane < 8) fdv[lane] = fminf(fmaxf(F_diag[lane], 0.9f), 1.1f);
    if (lane < 4) fvv[lane] = 1.0f / (1.0f + expf(-F_vel[lane]));
    const float qv = expf(q_scale[0]);
    const float rv = expf(r_scale[0]);

    const int e0 = lane, e1 = lane + 32;
    C[e0] = ((e0 >> 3) == (e0 & 7)) ? 1.0f : 0.0f;
    C[e1] = ((e1 >> 3) == (e1 & 7)) ? 1.0f : 0.0f;
    __syncwarp();

    float cold1_a = C[e0], cold1_b = C[e1];
    float cold2_a = 0.f,   cold2_b = 0.f;

    for (int t = 1; t < T_STEPS; ++t) {
#pragma unroll
        for (int h = 0; h < 2; h++) {
            int e = lane + h * 32;
            int i = e >> 3, j = e & 7;
            float fdi = fdv[i], fdj = fdv[j];
            float v = fdi * fdj * C[i * 8 + j];
            if (j < 4) v += fdi * fvv[j] * C[i * 8 + j + 4];
            if (i < 4) {
                float fvi = fvv[i];
                v += fvi * fdj * C[(i + 4) * 8 + j];
                if (j < 4) v += fvi * fvv[j] * C[(i + 4) * 8 + j + 4];
            }
            if (i == j) v += qv;
            P[e] = v;
        }
        __syncwarp();

        {
            int a = (lane >> 2) & 3, b = lane & 3;
            int r0 = 0 + (0 >= a), r1 = 1 + (1 >= a), r2 = 2 + (2 >= a);
            int c0 = 0 + (0 >= b), c1 = 1 + (1 >= b), c2 = 2 + (2 >= b);
            auto S = [&](int x, int y) -> float {
                float v = P[x * 8 + y];
                return (x == y) ? v + rv : v;
            };
            float m00 = S(r0, c0), m01 = S(r0, c1), m02 = S(r0, c2);
            float m10 = S(r1, c0), m11 = S(r1, c1), m12 = S(r1, c2);
            float m20 = S(r2, c0), m21 = S(r2, c1), m22 = S(r2, c2);
            float det3 = m00 * (m11 * m22 - m12 * m21)
                       - m01 * (m10 * m22 - m12 * m20)
                       + m02 * (m10 * m21 - m11 * m20);
            float cof = ((a + b) & 1) ? -det3 : det3;
            float c0v = __shfl_sync(FULLM, cof, 0);
            float c1v = __shfl_sync(FULLM, cof, 4);
            float c2v = __shfl_sync(FULLM, cof, 8);
            float c3v = __shfl_sync(FULLM, cof, 12);
            float det = S(0, 0) * c0v + S(1, 0) * c1v + S(2, 0) * c2v + S(3, 0) * c3v;
            float idet = __fdividef(1.0f, det);
            if (lane < 16) Sinv[b * 4 + a] = cof * idet;
        }
        __syncwarp();

        {
            int i = lane >> 2, m = lane & 3;
            float kv = P[i * 8 + 0] * Sinv[0 * 4 + m]
                     + P[i * 8 + 1] * Sinv[1 * 4 + m]
                     + P[i * 8 + 2] * Sinv[2 * 4 + m]
                     + P[i * 8 + 3] * Sinv[3 * 4 + m];
            Ksh[lane] = kv;
            g_Kall[t * 32 + lane] = kv;
        }
        __syncwarp();

        float na, nb;
        {
            int i0 = e0 >> 3, j0 = e0 & 7;
            float v = P[e0];
            v -= Ksh[i0 * 4 + 0] * P[0 * 8 + j0];
            v -= Ksh[i0 * 4 + 1] * P[1 * 8 + j0];
            v -= Ksh[i0 * 4 + 2] * P[2 * 8 + j0];
            v -= Ksh[i0 * 4 + 3] * P[3 * 8 + j0];
            na = v;
            int i1 = e1 >> 3, j1 = e1 & 7;
            float u = P[e1];
            u -= Ksh[i1 * 4 + 0] * P[0 * 8 + j1];
            u -= Ksh[i1 * 4 + 1] * P[1 * 8 + j1];
            u -= Ksh[i1 * 4 + 2] * P[2 * 8 + j1];
            u -= Ksh[i1 * 4 + 3] * P[3 * 8 + j1];
            nb = u;
        }
        int conv1 = __all_sync(FULLM, (na == cold1_a) && (nb == cold1_b));
        int conv2 = __all_sync(FULLM, (na == cold2_a) && (nb == cold2_b)) && (t >= 3);
        cold2_a = cold1_a; cold2_b = cold1_b;
        cold1_a = na;      cold1_b = nb;
        C[e0] = na; C[e1] = nb;
        __syncwarp();

        if (conv1) {
            float kA = Ksh[lane];
            for (int u = t + 1; u < T_STEPS; ++u) g_Kall[u * 32 + lane] = kA;
            return;
        }
        if (conv2) {
            float kA = Ksh[lane];
            float kB = g_Kall[(t - 1) * 32 + lane];
            for (int u = t + 1; u < T_STEPS; ++u)
                g_Kall[u * 32 + lane] = ((u - t) & 1) ? kB : kA;
            return;
        }
    }
}

// ---------------- Kernel 2: packed-f32x2 affine consumers ------------------

__device__ __forceinline__ float qsel(float4 v, int q) {
    float lo = (q & 1) ? v.y : v.x;
    float hi = (q & 1) ? v.w : v.z;
    return (q & 2) ? hi : lo;
}
__device__ __forceinline__ float qred(float v) {
    v += __shfl_xor_sync(FULLM, v, 1, 4);
    v += __shfl_xor_sync(FULLM, v, 2, 4);
    return v;
}
__device__ __forceinline__ float dot4(float4 a, float x0, float x1, float x2, float x3) {
    return fmaf(a.w, x3, fmaf(a.z, x2, fmaf(a.y, x1, a.x * x0)));
}

__global__ void __launch_bounds__(64, 1)
consumer_kernel(const float* __restrict__ meas,
                const float* __restrict__ F_diag,
                const float* __restrict__ F_vel,
                const float* __restrict__ mw,
                const float* __restrict__ W1,
                const float* __restrict__ b1,
                const float* __restrict__ g1,
                const float* __restrict__ be1,
                const float* __restrict__ W2,
                const float* __restrict__ b2,
                float* __restrict__ out)
{
    const int lane = threadIdx.x & 31;
    const int warp = threadIdx.x >> 5;
    const int q    = lane & 3;
    const int b    = blockIdx.x * 16 + warp * 8 + (lane >> 2);

    // lane-partitioned F: lane q owns state components q and q+4
    const float fdq  = fminf(fmaxf(F_diag[q], 0.9f), 1.1f);
    const float fdq4 = fminf(fmaxf(F_diag[q + 4], 0.9f), 1.1f);
    const float fvq  = 1.0f / (1.0f + expf(-F_vel[q]));
    const float smw  = 1.0f / (1.0f + expf(-mw[0]));
    const float b2s  = b2[0];
    const u64p  FD2  = pk2(fdq, fdq4);
    const u64p  NEG2 = pk2(-1.0f, -1.0f);

    // lane q owns hidden units 4q..4q+3; packed as pairs (0,1) and (2,3)
    u64p W1A0[4], W1A1[4], W1B0[4], W1B1[4];
    u64p B1p0, B1p1, G1p0, G1p1;
    float bev[4], w2v[4], g1s[4], b1s[4], w1as[4][4], w1bs[4][4];
#pragma unroll
    for (int k = 0; k < 4; k++) {
        int u = 4 * q + k;
#pragma unroll
        for (int j = 0; j < 4; j++) { w1as[k][j] = W1[u * 8 + j]; w1bs[k][j] = W1[u * 8 + 4 + j]; }
        b1s[k] = b1[u]; g1s[k] = g1[u]; bev[k] = be1[u]; w2v[k] = W2[u];
    }
#pragma unroll
    for (int j = 0; j < 4; j++) {
        W1A0[j] = pk2(w1as[0][j], w1as[1][j]);
        W1A1[j] = pk2(w1as[2][j], w1as[3][j]);
        W1B0[j] = pk2(w1bs[0][j], w1bs[1][j]);
        W1B1[j] = pk2(w1bs[2][j], w1bs[3][j]);
    }
    B1p0 = pk2(b1s[0], b1s[1]); B1p1 = pk2(b1s[2], b1s[3]);
    G1p0 = pk2(g1s[0], g1s[1]); G1p1 = pk2(g1s[2], g1s[3]);

    const float4* zr = (const float4*)(meas + (size_t)b * T_STEPS * 4);
    float* outp = out + (size_t)b * T_STEPS * 4;
    const float4* K4 = (const float4*)g_Kall;

    // ---- prologue: step-1 coefficient set (w-linear parts zero) ----
    float4 z0v = __ldg(&zr[0]);
    float4 z1v = __ldg(&zr[1]);
    float z0q = qsel(z0v, q);
    outp[q] = z0q;

    float PAq = fdq * z0q;
    float zfq = qsel(z1v, q) - PAq;
    float zf0 = __shfl_sync(FULLM, zfq, 0, 4);
    float zf1 = __shfl_sync(FULLM, zfq, 1, 4);
    float zf2 = __shfl_sync(FULLM, zfq, 2, 4);
    float zf3 = __shfl_sync(FULLM, zfq, 3, 4);

    float4 k1r0 = __ldg(&K4[1 * 8 + q]);
    float4 k1r1 = __ldg(&K4[1 * 8 + 4 + q]);
    u64p G12 = pk2(dot4(k1r0, zf0, zf1, zf2, zf3), dot4(k1r1, zf0, zf1, zf2, zf3));
    u64p G22 = pk2(0.f, 0.f);
    u64p PA2 = pk2(PAq, 0.f);
    u64p PB2 = pk2(0.f, 0.f);

    float Avs[4];
#pragma unroll
    for (int k = 0; k < 4; k++) {
        float a = fmaf(w1bs[k][0], z1v.x, b1s[k]);
        a = fmaf(w1bs[k][1], z1v.y, a);
        a = fmaf(w1bs[k][2], z1v.z, a);
        a = fmaf(w1bs[k][3], z1v.w, a);
        a = fmaf(w1as[k][0], zf0, a);
        a = fmaf(w1as[k][1], zf1, a);
        a = fmaf(w1as[k][2], zf2, a);
        a = fmaf(w1as[k][3], zf3, a);
        Avs[k] = a;
    }
    float C0, C1 = 0.f, C2 = 0.f;
    u64p PGp0, PGp1, QGp0 = pk2(0.f, 0.f), QGp1 = pk2(0.f, 0.f);
    {
        float sa  = qred((Avs[0] + Avs[1]) + (Avs[2] + Avs[3]));
        float saa = qred(fmaf(Avs[0], Avs[0], fmaf(Avs[1], Avs[1],
                     fmaf(Avs[2], Avs[2], Avs[3] * Avs[3]))));
        float mA = sa * 0.0625f;
        C0 = fmaf(-mA, mA, fmaf(saa, 0.0625f, 1e-5f));
        PGp0 = pk2((Avs[0] - mA) * g1s[0], (Avs[1] - mA) * g1s[1]);
        PGp1 = pk2((Avs[2] - mA) * g1s[2], (Avs[3] - mA) * g1s[3]);
    }

    float4 kcur0 = __ldg(&K4[2 * 8 + q]);
    float4 kcur1 = __ldg(&K4[2 * 8 + 4 + q]);
    float4 znext = __ldg(&zr[2]);
    float wprev = 0.f;

#pragma unroll 2
    for (int s = 1; s < T_STEPS; ++s) {
        int fi = min(s + 2, T_STEPS - 1);
        float4 zfut = __ldg(&zr[fi]);
        float4 kf0  = __ldg(&K4[fi * 8 + q]);
        float4 kf1  = __ldg(&K4[fi * 8 + 4 + q]);

        // ======== serial chain: w_s from wprev + coefficient set ========
        float wp  = wprev;
        u64p wp2  = pk2(wp, wp);
        float rstd = rsqrtf(fmaf(C2, wp * wp, fmaf(C1, wp, C0)));  // +eps in C0
        float t0, t1, t2, t3;
        upk2(ffma2(QGp0, wp2, PGp0), t0, t1);
        upk2(ffma2(QGp1, wp2, PGp1), t2, t3);
        float n0 = fmaxf(fmaf(t0, rstd, bev[0]), 0.f) * w2v[0];
        float n1 = fmaxf(fmaf(t1, rstd, bev[1]), 0.f) * w2v[1];
        float n2 = fmaxf(fmaf(t2, rstd, bev[2]), 0.f) * w2v[2];
        float n3 = fmaxf(fmaf(t3, rstd, bev[3]), 0.f) * w2v[3];
        float y  = (n0 + n1) + (n2 + n3);
        y += __shfl_xor_sync(FULLM, y, 1, 4);
        y += __shfl_xor_sync(FULLM, y, 2, 4);
        float w = sigmoid_fast(y + b2s) * smw;                     // w_s

        // ======== concrete state for step s (packed) ========
        u64p p2   = ffma2(wp2, PB2, PA2);
        u64p kin2 = ffma2(wp2, G22, G12);
        float pq, pq4, knq, knq4;
        upk2(p2, pq, pq4);
        upk2(kin2, knq, knq4);
        outp[s * 4 + q] = fmaf(w, knq, pq);

        float tl, th, ul, uh;
        upk2(fmul2(FD2, p2), tl, th);
        float Fpq  = fmaf(fvq, pq4, tl);
        float Fpq4 = th;
        upk2(fmul2(FD2, kin2), ul, uh);
        float Fkq  = fmaf(fvq, knq4, ul);
        float Fkq4 = uh;

        // ======== quad broadcasts ========
        float zq = qsel(znext, q) - Fpq;
        float z0_ = __shfl_sync(FULLM, zq, 0, 4);
        float z1_ = __shfl_sync(FULLM, zq, 1, 4);
        float z2_ = __shfl_sync(FULLM, zq, 2, 4);
        float z3_ = __shfl_sync(FULLM, zq, 3, 4);
        float g0_ = __shfl_sync(FULLM, Fkq, 0, 4);
        float g1_ = __shfl_sync(FULLM, Fkq, 1, 4);
        float g2_ = __shfl_sync(FULLM, Fkq, 2, 4);
        float g3_ = __shfl_sync(FULLM, Fkq, 3, 4);

        u64p z0p = pk2(z0_, z0_), z1p = pk2(z1_, z1_);
        u64p z2p = pk2(z2_, z2_), z3p = pk2(z3_, z3_);
        u64p g0p = pk2(g0_, g0_), g1p = pk2(g1_, g1_);
        u64p g2p = pk2(g2_, g2_), g3p = pk2(g3_, g3_);

        // ======== next-step coefficients (packed) ========
        u64p KP0 = pk2(kcur0.x, kcur1.x), KP1 = pk2(kcur0.y, kcur1.y);
        u64p KP2 = pk2(kcur0.z, kcur1.z), KP3 = pk2(kcur0.w, kcur1.w);
        G12 = ffma2(KP3, z3p, ffma2(KP2, z2p, ffma2(KP1, z1p, fmul2(KP0, z0p))));
        G22 = fmul2(ffma2(KP3, g3p, ffma2(KP2, g2p, ffma2(KP1, g1p, fmul2(KP0, g0p)))), NEG2);
        PA2 = pk2(Fpq, Fpq4);
        PB2 = pk2(Fkq, Fkq4);

        u64p zxp = pk2(znext.x, znext.x), zyp = pk2(znext.y, znext.y);
        u64p zzp = pk2(znext.z, znext.z), zwp = pk2(znext.w, znext.w);

        u64p Ap0 = ffma2(W1B0[3], zwp, ffma2(W1B0[2], zzp, ffma2(W1B0[1], zyp, ffma2(W1B0[0], zxp, B1p0))));
        Ap0 = ffma2(W1A0[3], z3p, ffma2(W1A0[2], z2p, ffma2(W1A0[1], z1p, ffma2(W1A0[0], z0p, Ap0))));
        u64p Ap1 = ffma2(W1B1[3], zwp, ffma2(W1B1[2], zzp, ffma2(W1B1[1], zyp, ffma2(W1B1[0], zxp, B1p1))));
        Ap1 = ffma2(W1A1[3], z3p, ffma2(W1A1[2], z2p, ffma2(W1A1[1], z1p, ffma2(W1A1[0], z0p, Ap1))));

        u64p Bp0 = fmul2(ffma2(W1A0[3], g3p, ffma2(W1A0[2], g2p,
                         ffma2(W1A0[1], g1p, fmul2(W1A0[0], g0p)))), NEG2);
        u64p Bp1 = fmul2(ffma2(W1A1[3], g3p, ffma2(W1A1[2], g2p,
                         ffma2(W1A1[1], g1p, fmul2(W1A1[0], g0p)))), NEG2);

        // LN polynomial sums (packed pair-reduce, then scalar quad-reduce)
        float lo, hi;
        float sa, sb, saa, sab, sbb;
        upk2(fadd2(Ap0, Ap1), lo, hi);  sa  = lo + hi;
        upk2(fadd2(Bp0, Bp1), lo, hi);  sb  = lo + hi;
        upk2(ffma2(Ap1, Ap1, fmul2(Ap0, Ap0)), lo, hi); saa = lo + hi;
        upk2(ffma2(Ap1, Bp1, fmul2(Ap0, Bp0)), lo, hi); sab = lo + hi;
        upk2(ffma2(Bp1, Bp1, fmul2(Bp0, Bp0)), lo, hi); sbb = lo + hi;
        sa = qred(sa); sb = qred(sb); saa = qred(saa); sab = qred(sab); sbb = qred(sbb);

        float mA = sa * 0.0625f, mB = sb * 0.0625f;
        C0 = fmaf(-mA, mA, fmaf(saa, 0.0625f, 1e-5f));
        C1 = 2.0f * fmaf(-mA, mB, sab * 0.0625f);
        C2 = fmaf(-mB, mB, sbb * 0.0625f);

        u64p mAn = pk2(-mA, -mA), mBn = pk2(-mB, -mB);
        PGp0 = fmul2(fadd2(Ap0, mAn), G1p0);
        PGp1 = fmul2(fadd2(Ap1, mAn), G1p1);
        QGp0 = fmul2(fadd2(Bp0, mBn), G1p0);
        QGp1 = fmul2(fadd2(Bp1, mBn), G1p1);

        znext = zfut; kcur0 = kf0; kcur1 = kf1; wprev = w;
    }
}

extern "C" void kernel_launch(void* const* d_in, const int* in_sizes, int n_in,
                              void* d_out, int out_size) {
    const float* meas    = (const float*)d_in[0];
    const float* F_diag  = (const float*)d_in[1];
    const float* F_vel   = (const float*)d_in[2];
    // d_in[3] = H_base ([I4|0], exploited analytically)
    const float* q_scale = (const float*)d_in[4];
    const float* r_scale = (const float*)d_in[5];
    const float* mw      = (const float*)d_in[6];
    const float* W1      = (const float*)d_in[7];
    const float* b1      = (const float*)d_in[8];
    const float* g1      = (const float*)d_in[9];
    const float* be1     = (const float*)d_in[10];
    const float* W2      = (const float*)d_in[11];
    const float* b2      = (const float*)d_in[12];
    float* out = (float*)d_out;

    riccati_kernel<<<1, 32>>>(F_diag, F_vel, q_scale, r_scale);

    int B = in_sizes[0] / (T_STEPS * 4);           // 2048
    dim3 grid(B / 16);                             // 128 blocks x 2 warps, 8 seq/warp
    consumer_kernel<<<grid, 64>>>(
        meas, F_diag, F_vel, mw, W1, b1, g1, be1, W2, b2, out);
}